// round 11
// baseline (speedup 1.0000x reference)
#include <cuda_runtime.h>
#include <cuda_fp16.h>
#include <math.h>
#include <stdint.h>

#define NPTS 1024
#define NH   16
#define TPB  256

static __device__ __forceinline__ uint32_t smem_addr(const void* p) {
    return (uint32_t)__cvta_generic_to_shared(p);
}
static __device__ __forceinline__ uint32_t sw128(uint32_t o) { return o ^ ((o >> 3) & 0x70); }

static __device__ __forceinline__ void ldsm_x4(uint32_t& r0, uint32_t& r1,
                                               uint32_t& r2, uint32_t& r3, uint32_t a) {
    asm volatile("ldmatrix.sync.aligned.m8n8.x4.shared.b16 {%0,%1,%2,%3}, [%4];"
                 : "=r"(r0), "=r"(r1), "=r"(r2), "=r"(r3) : "r"(a));
}

static __device__ __forceinline__ void mma16816(float& d0, float& d1, float& d2, float& d3,
                                                uint32_t a0, uint32_t a1, uint32_t a2, uint32_t a3,
                                                uint32_t b0, uint32_t b1) {
    asm volatile("mma.sync.aligned.m16n8k16.row.col.f32.f16.f16.f32 "
                 "{%0,%1,%2,%3}, {%4,%5,%6,%7}, {%8,%9}, {%0,%1,%2,%3};"
                 : "+f"(d0), "+f"(d1), "+f"(d2), "+f"(d3)
                 : "r"(a0), "r"(a1), "r"(a2), "r"(a3), "r"(b0), "r"(b1));
}

// round-to-nearest-even via magic number (valid for |x| < 2^22)
static __device__ __forceinline__ float rne(float x) {
    return (x + 12582912.0f) - 12582912.0f;
}

// Fused kernel. grid = (1024 rows i, 2 d-blocks, B); block = 256 threads.
// Thread tid generates fp16 features for pair (i, j), j = (i + dbase + tid + 1) mod 1024,
// into SW128-swizzled SMEM row tid via 4 interleaved rotation chains (k = 4s + c).
// One early block barrier (weights); then each warp: __syncwarp -> ldmatrix -> HMMA -> stores.
// Covers every off-diagonal unordered pair once (distance-512 twice, bitwise identical);
// writes out[i,j,:] and out[j,i,:]. Diagonal written by d-block 0. Bias lives in the
// MMA accumulator init.
__global__ __launch_bounds__(TPB)
void relbias_kernel(const float* __restrict__ vec,  // [B,1024,3]
                    const float* __restrict__ W,    // [64,16]
                    const float* __restrict__ bias, // [16]
                    float* __restrict__ out) {
    __shared__ __align__(128) uint8_t sA[TPB * 128]; // fp16 features, SW128, row = pair
    __shared__ __align__(128) uint8_t sW[16 * 128];  // fp16 weights [n][f'], SW128

    int tid = threadIdx.x;
    int i     = blockIdx.x;
    int dbase = blockIdx.y << 8;
    int b     = blockIdx.z;
    long long bb = (long long)b * NPTS;

    // W[64,16] fp32 -> sW[n][f'] fp16, f' interleaved: f'=2k -> Ws[k], f'=2k+1 -> Wc[k]
    for (int idx = tid; idx < 64 * 16; idx += TPB) {
        int n = idx & 15, k = idx >> 4;
        int fp = (k < 32) ? (2 * k) : (2 * (k - 32) + 1);
        *(__half*)(sW + sw128((uint32_t)n * 128u + (uint32_t)fp * 2u)) = __float2half_rn(W[idx]);
    }
    // diagonal (exact fp32): out[b,i,i,:] = bias + sum_k Wc[k,:]
    if (blockIdx.y == 0 && tid < NH) {
        float a = bias[tid];
#pragma unroll
        for (int k = 0; k < 32; ++k) a += W[(32 + k) * NH + tid];
        out[((bb + i) * NPTS + i) * NH + tid] = a;
    }
    __syncthreads();   // the ONLY block-wide barrier (sW ready)

    // ---- per-thread pair: angle ----
    int j = (i + dbase + tid + 1) & (NPTS - 1);
    const float* vb = vec + (size_t)b * NPTS * 3;
    float ax = vb[i * 3 + 0], ay = vb[i * 3 + 1], az = vb[i * 3 + 2];
    float bx = vb[j * 3 + 0], by = vb[j * 3 + 1], bz = vb[j * 3 + 2];
    float ra = rsqrtf(ax * ax + ay * ay + az * az);
    float rb = rsqrtf(bx * bx + by * by + bz * bz);
    float dx = ax * ra - bx * rb;
    float dy = ay * ra - by * rb;
    float dz = az * ra - bz * rb;
    float dot = 1.0f - 0.5f * ((dx * dx + dy * dy) + dz * dz);
    dot = fminf(fmaxf(dot, -1.0f), 1.0f);
    float t = acosf(dot) * 200.0f * (10.0f / 31.0f);

    // fp32 Cody-Waite mod 2*pi (magic-number rounding)
    float q  = rne(t * 0.15915494309189535f);
    float tr = fmaf(q, -6.28125f, t);
    tr = fmaf(q, -1.9353071795864769e-3f, tr);
    float s1 = __sinf(tr), c1 = __cosf(tr);

    // anchors for 4 chains via angle-addition (one MUFU pair total)
    float s2 = 2.0f * s1 * c1;
    float c2 = fmaf(-2.0f * s1, s1, 1.0f);
    float s3 = fmaf(s1, c2, c1 * s2);
    float c3 = fmaf(c1, c2, -(s1 * s2));
    float s4 = 2.0f * s2 * c2;                 // step rot = 4*tr
    float c4s = fmaf(-2.0f * s2, s2, 1.0f);

    float S0 = 0.0f, C0 = 1.0f;
    float S1 = s1,   C1 = c1;
    float S2 = s2,   C2 = c2;
    float S3 = s3,   C3 = c3;

    // ---- feature gen: 8 steps, one STS.128 each; 4 independent chains ----
    {
        uint32_t base_t = smem_addr(sA) + (uint32_t)tid * 128u;
        uint32_t xr = ((uint32_t)tid & 7u) << 4;
#pragma unroll
        for (int s = 0; s < 8; ++s) {
            __half2 h0 = __floats2half2_rn(S0, C0);
            __half2 h1 = __floats2half2_rn(S1, C1);
            __half2 h2h = __floats2half2_rn(S2, C2);
            __half2 h3 = __floats2half2_rn(S3, C3);
            asm volatile("st.shared.v4.b32 [%0], {%1,%2,%3,%4};"
                         :: "r"(base_t + (((uint32_t)s * 16u) ^ xr)),
                            "r"(*(uint32_t*)&h0), "r"(*(uint32_t*)&h1),
                            "r"(*(uint32_t*)&h2h), "r"(*(uint32_t*)&h3) : "memory");
            float nS0 = fmaf(S0, c4s, C0 * s4); float nC0 = fmaf(C0, c4s, -(S0 * s4));
            float nS1 = fmaf(S1, c4s, C1 * s4); float nC1 = fmaf(C1, c4s, -(S1 * s4));
            float nS2 = fmaf(S2, c4s, C2 * s4); float nC2 = fmaf(C2, c4s, -(S2 * s4));
            float nS3 = fmaf(S3, c4s, C3 * s4); float nC3 = fmaf(C3, c4s, -(S3 * s4));
            S0 = nS0; C0 = nC0; S1 = nS1; C1 = nC1;
            S2 = nS2; C2 = nC2; S3 = nS3; C3 = nC3;
        }
    }

    __syncwarp();   // warp-local: this warp's 32 A-rows are ready

    // ---- HMMA: each warp computes its own 32 pairs x 16 heads ----
    int wid = tid >> 5, lane = tid & 31;
    int wbase = wid << 5;
    int c4 = lane & 3;

    // B fragments from sW: bfrag[ntile][ktile][2]
    uint32_t bfrag[2][4][2];
    uint32_t sWb = smem_addr(sW);
#pragma unroll
    for (int nt = 0; nt < 2; ++nt) {
#pragma unroll
        for (int ktp = 0; ktp < 2; ++ktp) {
            uint32_t n = (uint32_t)(nt * 8 + (lane & 7));
            uint32_t a = sWb + n * 128u
                       + ((((uint32_t)ktp * 64u) + ((uint32_t)(lane >> 3) * 16u)) ^ ((n & 7u) << 4));
            ldsm_x4(bfrag[nt][2 * ktp][0], bfrag[nt][2 * ktp][1],
                    bfrag[nt][2 * ktp + 1][0], bfrag[nt][2 * ktp + 1][1], a);
        }
    }

    // accumulators initialized with bias (acc[mt][nt][e] -> head col nt*8 + 2*c4 + (e&1))
    float2 bz0 = *(const float2*)(bias + 2 * c4);
    float2 bz1 = *(const float2*)(bias + 8 + 2 * c4);
    float acc[2][2][4];
#pragma unroll
    for (int mt = 0; mt < 2; ++mt) {
        acc[mt][0][0] = bz0.x; acc[mt][0][1] = bz0.y;
        acc[mt][0][2] = bz0.x; acc[mt][0][3] = bz0.y;
        acc[mt][1][0] = bz1.x; acc[mt][1][1] = bz1.y;
        acc[mt][1][2] = bz1.x; acc[mt][1][3] = bz1.y;
    }

    uint32_t sAb = smem_addr(sA);
#pragma unroll
    for (int mt = 0; mt < 2; ++mt) {
#pragma unroll
        for (int kt = 0; kt < 4; ++kt) {
            uint32_t row = (uint32_t)(wbase + mt * 16 + (lane & 15));
            uint32_t a = sAb + row * 128u
                       + ((((uint32_t)kt * 32u) + ((uint32_t)(lane >> 4) * 16u)) ^ ((row & 7u) << 4));
            uint32_t a0, a1, a2, a3;
            ldsm_x4(a0, a1, a2, a3, a);
#pragma unroll
            for (int nt = 0; nt < 2; ++nt)
                mma16816(acc[mt][nt][0], acc[mt][nt][1], acc[mt][nt][2], acc[mt][nt][3],
                         a0, a1, a2, a3, bfrag[nt][kt][0], bfrag[nt][kt][1]);
        }
    }

    // ---- epilogue: bfly-shuffle into float4, symmetric STG.128 ----
    int colbase = (c4 & 1) * 8 + (c4 & 2) * 2;           // c0:0 c1:8 c2:4 c3:12
#pragma unroll
    for (int mt = 0; mt < 2; ++mt) {
#pragma unroll
        for (int h = 0; h < 2; ++h) {
            float2 v0 = make_float2(acc[mt][0][2 * h], acc[mt][0][2 * h + 1]);
            float2 v1 = make_float2(acc[mt][1][2 * h], acc[mt][1][2 * h + 1]);
            // even lanes send nt1, odd lanes send nt0; exchange with lane^1
            float2 snd = (c4 & 1) ? v0 : v1;
            double sd = *reinterpret_cast<double*>(&snd);
            double rd = __shfl_xor_sync(0xffffffffu, sd, 1);
            float2 rcv = *reinterpret_cast<float2*>(&rd);
            float4 res = (c4 & 1) ? make_float4(rcv.x, rcv.y, v1.x, v1.y)
                                  : make_float4(v0.x, v0.y, rcv.x, rcv.y);
            int p  = wbase + mt * 16 + h * 8 + (lane >> 2);
            int jp = (i + dbase + p + 1) & (NPTS - 1);
            __stcs((float4*)(out + ((bb + i) * NPTS + jp) * NH + colbase), res);
            __stcs((float4*)(out + ((bb + jp) * NPTS + i) * NH + colbase), res);
        }
    }
}

extern "C" void kernel_launch(void* const* d_in, const int* in_sizes, int n_in,
                              void* d_out, int out_size) {
    const float* vec_map = (const float*)d_in[0];
    const float* kernelW = (const float*)d_in[1];
    const float* bias    = (const float*)d_in[2];
    float* out = (float*)d_out;

    int total_vecs = in_sizes[0] / 3;   // B * N
    int B = total_vecs / NPTS;

    dim3 grid(NPTS, 2, B);
    relbias_kernel<<<grid, TPB>>>(vec_map, kernelW, bias, out);
}